// round 2
// baseline (speedup 1.0000x reference)
#include <cuda_runtime.h>
#include <cstdint>

#define ROW_LEN 4096
#define K_TOP   64
#define THREADS 512
#define EPT     8
#define NWARP   16

__device__ __forceinline__ uint32_t f2k(float f) {
    uint32_t u = __float_as_uint(f);
    return u ^ ((uint32_t)((int32_t)u >> 31) | 0x80000000u);   // SHF + LOP3
}
__device__ __forceinline__ uint32_t k2u(uint32_t k) {
    uint32_t m = (uint32_t)((int32_t)k >> 31);
    return k ^ (~m | 0x80000000u);                             // SHF + LOP3
}

__global__ __launch_bounds__(THREADS, 3)
void topk_mask_kernel(const float* __restrict__ x, float* __restrict__ out) {
    const int row  = blockIdx.x;
    const int tid  = threadIdx.x;
    const int lane = tid & 31;
    const int wid  = tid >> 5;
    const unsigned lml = (1u << lane) - 1u;

    const float4* xrow = reinterpret_cast<const float4*>(x + (size_t)row * ROW_LEN);
    float4*       orow = reinterpret_cast<float4*>(out + (size_t)row * ROW_LEN);

    // 16 KB: per-warp private histograms; later reused as candidate buffer (cap 4096 = full row)
    __shared__ __align__(16) uint32_t s_hist[NWARP][256];
    __shared__ uint32_t s_tot[256];
    __shared__ uint32_t s_S[256];        // suffix sums
    __shared__ uint32_t s_sel[2];
    __shared__ uint32_t s_wcnt[NWARP];
    __shared__ uint32_t s_woff[NWARP];
    __shared__ uint32_t s_nc;
    __shared__ uint32_t s_wsum[NWARP];
    uint32_t* cand = &s_hist[0][0];

    // ---- load (streaming, read-once) + monotonic key transform ----
    float4 v0 = __ldcs(&xrow[2 * tid]);
    float4 v1 = __ldcs(&xrow[2 * tid + 1]);
    uint32_t keys[EPT];
    keys[0] = f2k(v0.x); keys[1] = f2k(v0.y); keys[2] = f2k(v0.z); keys[3] = f2k(v0.w);
    keys[4] = f2k(v1.x); keys[5] = f2k(v1.y); keys[6] = f2k(v1.z); keys[7] = f2k(v1.w);

    // ---- zero private histograms (vectorized) ----
    {
        uint4 z = make_uint4(0, 0, 0, 0);
        uint4* h4 = reinterpret_cast<uint4*>(&s_hist[0][0]);
        #pragma unroll
        for (int i = 0; i < 2; ++i) h4[tid + i * THREADS] = z;
    }
    __syncthreads();

    // ---- single 8-bit histogram pass, per-warp private, no atomics ----
    {
        uint32_t* myh = &s_hist[wid][0];
        #pragma unroll
        for (int j = 0; j < EPT; ++j) {
            uint32_t bin = keys[j] >> 24;
            unsigned peers = __match_any_sync(0xffffffffu, bin);
            if (lane == __ffs(peers) - 1)
                myh[bin] += (uint32_t)__popc(peers);
        }
    }
    __syncthreads();

    // ---- reduce 16 private histograms (conflict-free column reads) ----
    if (tid < 256) {
        uint32_t s = 0;
        #pragma unroll
        for (int w = 0; w < NWARP; ++w) s += s_hist[w][tid];
        s_tot[tid] = s;
    }
    __syncthreads();

    // ---- warp0 suffix sums S[b] = sum_{j>=b} tot[j] ----
    if (tid < 32) {
        uint32_t local[8];
        uint32_t s = 0;
        #pragma unroll
        for (int j = 0; j < 8; ++j) {
            int b = 255 - (tid * 8 + j);
            s += s_tot[b];
            local[j] = s;
        }
        uint32_t incl = s;
        #pragma unroll
        for (int off = 1; off < 32; off <<= 1) {
            uint32_t n = __shfl_up_sync(0xffffffffu, incl, off);
            if (tid >= off) incl += n;
        }
        uint32_t excl = incl - s;
        #pragma unroll
        for (int j = 0; j < 8; ++j) {
            int b = 255 - (tid * 8 + j);
            s_S[b] = excl + local[j];
        }
    }
    __syncthreads();

    // ---- select threshold bin: S[b] >= K > S[b+1]; rem = K - S[b+1] ----
    if (tid < 256) {
        uint32_t above = (tid == 255) ? 0u : s_S[tid + 1];
        if (s_S[tid] >= K_TOP && above < K_TOP) {
            s_sel[0] = (uint32_t)tid;
            s_sel[1] = K_TOP - above;
        }
    }
    __syncthreads();
    const uint32_t sel = s_sel[0];
    const uint32_t rem = s_sel[1];

    // ---- compact candidates (top byte == sel) into smem (reusing hist space) ----
    uint32_t mycnt = 0;
    #pragma unroll
    for (int j = 0; j < EPT; ++j) mycnt += ((keys[j] >> 24) == sel);
    uint32_t wc = __reduce_add_sync(0xffffffffu, mycnt);
    if (lane == 0) s_wcnt[wid] = wc;
    __syncthreads();
    if (tid < 32) {
        uint32_t c = (lane < NWARP) ? s_wcnt[lane] : 0u;
        uint32_t incl = c;
        #pragma unroll
        for (int off = 1; off < 32; off <<= 1) {
            uint32_t n = __shfl_up_sync(0xffffffffu, incl, off);
            if (tid >= off) incl += n;
        }
        if (lane < NWARP) s_woff[lane] = incl - c;
        if (lane == NWARP - 1) s_nc = incl;
    }
    __syncthreads();
    {
        uint32_t pos = s_woff[wid];
        #pragma unroll
        for (int j = 0; j < EPT; ++j) {
            bool f = ((keys[j] >> 24) == sel);
            unsigned bal = __ballot_sync(0xffffffffu, f);
            if (f) cand[pos + __popc(bal & lml)] = keys[j];
            pos += (uint32_t)__popc(bal);
        }
    }
    const uint32_t nc  = s_nc;
    const uint32_t ncp = (nc + 31u) & ~31u;
    for (uint32_t i = nc + tid; i < ncp; i += THREADS) cand[i] = 0;   // pad (key 0 < any candidate)
    __syncthreads();

    // ---- warp0: exact k-th key via value binary search with count==rem early exit ----
    if (tid < 32) {
        uint32_t lo = sel << 24;
        uint32_t hi = (sel << 24) | 0x00FFFFFFu;
        const uint32_t m = ncp >> 5;
        uint32_t T = 0;
        bool done = false;
        while (lo < hi) {
            uint32_t mid = lo + ((hi - lo + 1u) >> 1);   // mid >= lo+1 >= 1, excludes pad zeros
            uint32_t c = 0, mn = 0xFFFFFFFFu;
            for (uint32_t i = 0; i < m; ++i) {
                uint32_t v = cand[i * 32 + lane];
                if (v >= mid) { c++; mn = min(mn, v); }
            }
            c = __reduce_add_sync(0xffffffffu, c);
            if (c == rem) { T = __reduce_min_sync(0xffffffffu, mn); done = true; break; }
            if (c > rem) lo = mid; else hi = mid - 1u;
        }
        if (!done) T = lo;
        uint32_t g = 0;
        for (uint32_t i = 0; i < m; ++i) g += (cand[i * 32 + lane] > T);
        g = __reduce_add_sync(0xffffffffu, g);
        if (lane == 0) { s_sel[0] = T; s_sel[1] = rem - g; }   // rem2 = # of T-ties to keep
    }
    __syncthreads();
    const uint32_t T    = s_sel[0];
    const uint32_t rem2 = s_sel[1];

    // ---- tie ranking: block exclusive scan of per-thread equal counts (index order) ----
    uint32_t cnt = 0;
    #pragma unroll
    for (int j = 0; j < EPT; ++j) cnt += (keys[j] == T);
    uint32_t incl = cnt;
    #pragma unroll
    for (int off = 1; off < 32; off <<= 1) {
        uint32_t n = __shfl_up_sync(0xffffffffu, incl, off);
        if (lane >= off) incl += n;
    }
    if (lane == 31) s_wsum[wid] = incl;
    __syncthreads();
    if (tid < NWARP) {
        uint32_t v = s_wsum[tid];
        #pragma unroll
        for (int off = 1; off < NWARP; off <<= 1) {
            uint32_t n = __shfl_up_sync(0xffffu, v, off);
            if (tid >= off) v += n;
        }
        s_wsum[tid] = v;
    }
    __syncthreads();
    uint32_t rank = ((wid > 0) ? s_wsum[wid - 1] : 0u) + (incl - cnt);

    // ---- masked write ----
    uint32_t o[EPT];
    #pragma unroll
    for (int j = 0; j < EPT; ++j) {
        bool gt = keys[j] > T;
        bool eq = keys[j] == T;
        bool inc = gt || (eq && rank < rem2);
        o[j] = inc ? k2u(keys[j]) : 0u;
        rank += eq;
    }
    float4 w0, w1;
    w0.x = __uint_as_float(o[0]); w0.y = __uint_as_float(o[1]);
    w0.z = __uint_as_float(o[2]); w0.w = __uint_as_float(o[3]);
    w1.x = __uint_as_float(o[4]); w1.y = __uint_as_float(o[5]);
    w1.z = __uint_as_float(o[6]); w1.w = __uint_as_float(o[7]);
    __stcs(&orow[2 * tid],     w0);
    __stcs(&orow[2 * tid + 1], w1);
}

extern "C" void kernel_launch(void* const* d_in, const int* in_sizes, int n_in,
                              void* d_out, int out_size) {
    const float* x = (const float*)d_in[0];
    float* out = (float*)d_out;
    int rows = in_sizes[0] / ROW_LEN;
    topk_mask_kernel<<<rows, THREADS>>>(x, out);
}

// round 3
// speedup vs baseline: 1.2148x; 1.2148x over previous
#include <cuda_runtime.h>
#include <cstdint>

#define ROW_LEN 4096
#define K_TOP   64
#define THREADS 512
#define EPT     8
#define NWARP   16

static __device__ __forceinline__ uint32_t f2k(float f) {
    uint32_t u = __float_as_uint(f);
    return u ^ ((uint32_t)((int32_t)u >> 31) | 0x80000000u);   // order-preserving
}
static __device__ __forceinline__ uint32_t k2u(uint32_t k) {
    uint32_t m = (uint32_t)((int32_t)k >> 31);
    return k ^ (~m | 0x80000000u);                             // inverse
}

__global__ __launch_bounds__(THREADS, 3)
void topk_mask_kernel(const float* __restrict__ x, float* __restrict__ out) {
    const int row  = blockIdx.x;
    const int tid  = threadIdx.x;
    const int lane = tid & 31;
    const int wid  = tid >> 5;

    __shared__ uint32_t s_hist[2][256];   // double-buffered histograms
    __shared__ uint32_t s_sel;            // packed: bin | rem_new<<8 | cnt<<16
    __shared__ uint32_t s_wsum[NWARP];

    const float4* xrow = reinterpret_cast<const float4*>(x + (size_t)row * ROW_LEN);
    float4*       orow = reinterpret_cast<float4*>(out + (size_t)row * ROW_LEN);

    // issue loads first (long latency), overlap with smem zeroing
    float4 v0 = __ldcs(&xrow[2 * tid]);
    float4 v1 = __ldcs(&xrow[2 * tid + 1]);
    if (tid < 256) s_hist[0][tid] = 0;

    uint32_t keys[EPT];
    keys[0] = f2k(v0.x); keys[1] = f2k(v0.y); keys[2] = f2k(v0.z); keys[3] = f2k(v0.w);
    keys[4] = f2k(v1.x); keys[5] = f2k(v1.y); keys[6] = f2k(v1.z); keys[7] = f2k(v1.w);
    __syncthreads();

    uint32_t prefix = 0;
    uint32_t rem = K_TOP;
    uint32_t T = 0, rem2 = 0;

    #pragma unroll 1
    for (int pass = 0; pass < 4; ++pass) {
        const int shift = 24 - 8 * pass;
        uint32_t* h = s_hist[pass & 1];
        const uint32_t hm = (pass == 0) ? 0u : (0xFFFFFFFFu << (shift + 8));

        // warp-aggregated histogram over current candidates
        #pragma unroll
        for (int j = 0; j < EPT; ++j) {
            if ((keys[j] & hm) == prefix) {
                uint32_t bin = (keys[j] >> shift) & 0xFFu;
                unsigned peers = __match_any_sync(__activemask(), bin);
                if (lane == __ffs(peers) - 1)
                    atomicAdd(&h[bin], (uint32_t)__popc(peers));
            }
        }
        __syncthreads();

        if (wid == 0) {
            // fused suffix-scan + crossing-bin select (warp 0 only)
            uint32_t local[8];
            uint32_t s = 0;
            #pragma unroll
            for (int j = 0; j < 8; ++j) {
                s += h[255 - (lane * 8 + j)];
                local[j] = s;
            }
            uint32_t incl = s;
            #pragma unroll
            for (int off = 1; off < 32; off <<= 1) {
                uint32_t n = __shfl_up_sync(0xffffffffu, incl, off);
                if (lane >= off) incl += n;
            }
            uint32_t excl = incl - s;   // S over bins handled by lower lanes (higher bins)
            #pragma unroll
            for (int j = 0; j < 8; ++j) {
                uint32_t S     = excl + local[j];
                uint32_t above = (j == 0) ? excl : (excl + local[j - 1]);
                if (S >= rem && above < rem) {
                    uint32_t bin = 255u - (uint32_t)(lane * 8 + j);
                    s_sel = bin | ((rem - above) << 8) | ((S - above) << 16);
                }
            }
        } else {
            // zero the other buffer for the next pass (overlapped with warp0 scan)
            int t2 = tid - 32;
            if (t2 < 256) s_hist[(pass + 1) & 1][t2] = 0;
        }
        __syncthreads();

        uint32_t packed = s_sel;
        uint32_t sel  = packed & 0xFFu;
        uint32_t rnew = (packed >> 8) & 0xFFu;
        uint32_t cnt  = packed >> 16;
        prefix |= sel << shift;
        rem = rnew;

        if (cnt == rem && prefix != 0) {
            // entire remaining bin is included: threshold is "key >= prefix"
            T = prefix - 1u;   // prefix >= 1 guaranteed by the guard
            rem2 = 0u;
            break;
        }
        if (pass == 3) {       // exact k-th key found
            T = prefix;
            rem2 = rem;        // number of T-ties to include (>=1)
        }
    }

    // tie ranking only when needed (uniform branch; rare)
    uint32_t rank = 0;
    if (rem2 > 0) {
        uint32_t cnt = 0;
        #pragma unroll
        for (int j = 0; j < EPT; ++j) cnt += (keys[j] == T);
        uint32_t incl = cnt;
        #pragma unroll
        for (int off = 1; off < 32; off <<= 1) {
            uint32_t n = __shfl_up_sync(0xffffffffu, incl, off);
            if (lane >= off) incl += n;
        }
        if (lane == 31) s_wsum[wid] = incl;
        __syncthreads();
        if (tid < NWARP) {
            uint32_t v = s_wsum[tid];
            #pragma unroll
            for (int off = 1; off < NWARP; off <<= 1) {
                uint32_t n = __shfl_up_sync(0xffffu, v, off);
                if (tid >= off) v += n;
            }
            s_wsum[tid] = v;
        }
        __syncthreads();
        rank = ((wid > 0) ? s_wsum[wid - 1] : 0u) + (incl - cnt);
    }

    // masked write: include keys > T, plus first rem2 (by index) keys == T
    uint32_t o[EPT];
    #pragma unroll
    for (int j = 0; j < EPT; ++j) {
        bool gt = keys[j] > T;
        bool eq = keys[j] == T;
        bool inc = gt || (eq && rank < rem2);
        o[j] = inc ? k2u(keys[j]) : 0u;
        rank += eq;
    }
    float4 w0, w1;
    w0.x = __uint_as_float(o[0]); w0.y = __uint_as_float(o[1]);
    w0.z = __uint_as_float(o[2]); w0.w = __uint_as_float(o[3]);
    w1.x = __uint_as_float(o[4]); w1.y = __uint_as_float(o[5]);
    w1.z = __uint_as_float(o[6]); w1.w = __uint_as_float(o[7]);
    __stcs(&orow[2 * tid],     w0);
    __stcs(&orow[2 * tid + 1], w1);
}

extern "C" void kernel_launch(void* const* d_in, const int* in_sizes, int n_in,
                              void* d_out, int out_size) {
    const float* x = (const float*)d_in[0];
    float* out = (float*)d_out;
    int rows = in_sizes[0] / ROW_LEN;
    topk_mask_kernel<<<rows, THREADS>>>(x, out);
}

// round 5
// speedup vs baseline: 1.7376x; 1.4303x over previous
#include <cuda_runtime.h>
#include <cstdint>

#define ROW_LEN 4096
#define K_TOP   64u
#define THREADS 512
#define EPT     8
#define NWARP   16

#define KP1 0xC0000000u   // f2k(2.0f)
#define KP2 0xBFC00000u   // f2k(1.5f)

static __device__ __forceinline__ uint32_t f2k(float f) {
    uint32_t u = __float_as_uint(f);
    return u ^ ((uint32_t)((int32_t)u >> 31) | 0x80000000u);
}
static __device__ __forceinline__ uint32_t k2u(uint32_t k) {
    uint32_t m = (uint32_t)((int32_t)k >> 31);
    return k ^ (~m | 0x80000000u);
}

__global__ __launch_bounds__(THREADS, 3)
void topk_mask_kernel(const float* __restrict__ x, float* __restrict__ out) {
    const int row  = blockIdx.x;
    const int tid  = threadIdx.x;
    const int lane = tid & 31;
    const int wid  = tid >> 5;

    __shared__ uint32_t s_cand[ROW_LEN];   // worst-case full row (16 KB)
    __shared__ uint32_t s_wtot[NWARP];
    __shared__ uint32_t s_woff[NWARP];
    __shared__ uint32_t s_T, s_rem2, s_eq;
    __shared__ uint32_t s_wsum[NWARP];

    const float4* xrow = reinterpret_cast<const float4*>(x + (size_t)row * ROW_LEN);
    float4*       orow = reinterpret_cast<float4*>(out + (size_t)row * ROW_LEN);

    float4 v0 = __ldcs(&xrow[2 * tid]);
    float4 v1 = __ldcs(&xrow[2 * tid + 1]);
    uint32_t keys[EPT];
    keys[0] = f2k(v0.x); keys[1] = f2k(v0.y); keys[2] = f2k(v0.z); keys[3] = f2k(v0.w);
    keys[4] = f2k(v1.x); keys[5] = f2k(v1.y); keys[6] = f2k(v1.z); keys[7] = f2k(v1.w);

    // ---- dual pivot counts, packed (lo 16: >=KP1, hi 16: >=KP2) ----
    uint32_t c1 = 0, c2 = 0;
    #pragma unroll
    for (int j = 0; j < EPT; ++j) {
        c1 += (keys[j] >= KP1);
        c2 += (keys[j] >= KP2);
    }
    uint32_t packed = c1 | (c2 << 16);

    // warp inclusive scan of packed counts (fields can't overflow 16 bits)
    uint32_t incl = packed;
    #pragma unroll
    for (int off = 1; off < 32; off <<= 1) {
        uint32_t n = __shfl_up_sync(0xffffffffu, incl, off);
        if (lane >= off) incl += n;
    }
    if (lane == 31) s_wtot[wid] = incl;
    __syncthreads();

    // 16-lane scan of warp totals
    if (tid < NWARP) {
        uint32_t v = s_wtot[tid];
        #pragma unroll
        for (int off = 1; off < NWARP; off <<= 1) {
            uint32_t n = __shfl_up_sync(0xffffu, v, off);
            if (tid >= off) v += n;
        }
        s_woff[tid] = v;  // inclusive warp prefix (packed)
    }
    __syncthreads();

    const uint32_t blockTot = s_woff[NWARP - 1];
    const uint32_t tot1 = blockTot & 0xFFFFu;
    const uint32_t tot2 = blockTot >> 16;
    const uint32_t wexcl = (wid > 0) ? s_woff[wid - 1] : 0u;
    const uint32_t texcl = wexcl + (incl - packed);   // thread-exclusive prefix, packed

    uint32_t pivot, nc, myoff;
    if (tot1 >= K_TOP)      { pivot = KP1; nc = tot1; myoff = texcl & 0xFFFFu; }
    else if (tot2 >= K_TOP) { pivot = KP2; nc = tot2; myoff = texcl >> 16; }
    else                    { pivot = 0u;  nc = ROW_LEN; myoff = (uint32_t)tid * EPT; }

    // ---- compact candidates (order irrelevant; ranking is value-based) ----
    #pragma unroll
    for (int j = 0; j < EPT; ++j) {
        if (keys[j] >= pivot) s_cand[myoff++] = keys[j];
    }
    __syncthreads();

    // ---- rank candidates: thread with the K-th largest publishes T ----
    for (uint32_t c = tid; c < nc; c += THREADS) {
        uint32_t mk = s_cand[c];
        uint32_t gt = 0, eq = 0;
        #pragma unroll 4
        for (uint32_t i = 0; i < nc; ++i) {     // broadcast LDS reads
            uint32_t v = s_cand[i];
            gt += (v > mk);
            eq += (v == mk);
        }
        if (gt < K_TOP && gt + eq >= K_TOP) {   // all T-ties hit this; same values written
            s_T = mk;
            s_rem2 = K_TOP - gt;
            s_eq = eq;
        }
    }
    __syncthreads();

    const uint32_t T    = s_T;
    const uint32_t rem2 = s_rem2;
    const uint32_t eqT  = s_eq;

    uint32_t o[EPT];
    if (eqT == rem2) {
        // common case: include every key >= T (covers unique-T and exact-fit ties)
        #pragma unroll
        for (int j = 0; j < EPT; ++j)
            o[j] = (keys[j] >= T) ? k2u(keys[j]) : 0u;
    } else {
        // rare: more T-ties than quota -> keep first rem2 by global index
        uint32_t cnt = 0;
        #pragma unroll
        for (int j = 0; j < EPT; ++j) cnt += (keys[j] == T);
        uint32_t ti = cnt;
        #pragma unroll
        for (int off = 1; off < 32; off <<= 1) {
            uint32_t n = __shfl_up_sync(0xffffffffu, ti, off);
            if (lane >= off) ti += n;
        }
        if (lane == 31) s_wsum[wid] = ti;
        __syncthreads();
        if (tid < NWARP) {
            uint32_t v = s_wsum[tid];
            #pragma unroll
            for (int off = 1; off < NWARP; off <<= 1) {
                uint32_t n = __shfl_up_sync(0xffffu, v, off);
                if (tid >= off) v += n;
            }
            s_wsum[tid] = v;
        }
        __syncthreads();
        uint32_t rank = ((wid > 0) ? s_wsum[wid - 1] : 0u) + (ti - cnt);
        #pragma unroll
        for (int j = 0; j < EPT; ++j) {
            bool eq = (keys[j] == T);
            bool inc = (keys[j] > T) || (eq && rank < rem2);
            o[j] = inc ? k2u(keys[j]) : 0u;
            rank += eq;
        }
    }

    float4 w0, w1;
    w0.x = __uint_as_float(o[0]); w0.y = __uint_as_float(o[1]);
    w0.z = __uint_as_float(o[2]); w0.w = __uint_as_float(o[3]);
    w1.x = __uint_as_float(o[4]); w1.y = __uint_as_float(o[5]);
    w1.z = __uint_as_float(o[6]); w1.w = __uint_as_float(o[7]);
    __stcs(&orow[2 * tid],     w0);
    __stcs(&orow[2 * tid + 1], w1);
}

extern "C" void kernel_launch(void* const* d_in, const int* in_sizes, int n_in,
                              void* d_out, int out_size) {
    const float* x = (const float*)d_in[0];
    float* out = (float*)d_out;
    int rows = in_sizes[0] / ROW_LEN;
    topk_mask_kernel<<<rows, THREADS>>>(x, out);
}

// round 6
// speedup vs baseline: 2.0317x; 1.1693x over previous
#include <cuda_runtime.h>
#include <cstdint>

#define ROW_LEN 4096
#define K_TOP   64u
#define THREADS 512
#define EPT     8
#define NWARP   16

#define P1 2.0f    // E[count >= P1] ~ 93  (>=64 w.p. ~0.999)
#define P2 1.5f    // E[count >= P2] ~ 274 (>=64 w.p. ~1-1e-40)

__global__ __launch_bounds__(THREADS, 4)
void topk_mask_kernel(const float* __restrict__ x, float* __restrict__ out) {
    const int row  = blockIdx.x;
    const int tid  = threadIdx.x;
    const int lane = tid & 31;
    const int wid  = tid >> 5;

    __shared__ float    s_cand[ROW_LEN];   // worst-case full row (16 KB)
    __shared__ uint32_t s_wtot[NWARP];
    __shared__ uint32_t s_woff[NWARP];
    __shared__ float    s_T;
    __shared__ uint32_t s_rem2, s_eq;
    __shared__ uint32_t s_wsum[NWARP];

    const float4* xrow = reinterpret_cast<const float4*>(x + (size_t)row * ROW_LEN);
    float4*       orow = reinterpret_cast<float4*>(out + (size_t)row * ROW_LEN);

    float4 a = __ldcs(&xrow[2 * tid]);
    float4 b = __ldcs(&xrow[2 * tid + 1]);
    float v[EPT];
    v[0] = a.x; v[1] = a.y; v[2] = a.z; v[3] = a.w;
    v[4] = b.x; v[5] = b.y; v[6] = b.z; v[7] = b.w;

    // ---- dual pivot counts, packed (lo 16: >=P1, hi 16: >=P2) ----
    uint32_t c1 = 0, c2 = 0;
    #pragma unroll
    for (int j = 0; j < EPT; ++j) {
        c1 += (v[j] >= P1);
        c2 += (v[j] >= P2);
    }
    uint32_t packed = c1 | (c2 << 16);

    // warp inclusive scan of packed counts
    uint32_t incl = packed;
    #pragma unroll
    for (int off = 1; off < 32; off <<= 1) {
        uint32_t n = __shfl_up_sync(0xffffffffu, incl, off);
        if (lane >= off) incl += n;
    }
    if (lane == 31) s_wtot[wid] = incl;
    __syncthreads();

    if (tid < NWARP) {
        uint32_t w = s_wtot[tid];
        #pragma unroll
        for (int off = 1; off < NWARP; off <<= 1) {
            uint32_t n = __shfl_up_sync(0xffffu, w, off);
            if (tid >= off) w += n;
        }
        s_woff[tid] = w;  // inclusive warp prefix (packed)
    }
    __syncthreads();

    const uint32_t blockTot = s_woff[NWARP - 1];
    const uint32_t tot1 = blockTot & 0xFFFFu;
    const uint32_t tot2 = blockTot >> 16;
    const uint32_t wexcl = (wid > 0) ? s_woff[wid - 1] : 0u;
    const uint32_t texcl = wexcl + (incl - packed);   // thread-exclusive prefix, packed

    float    pivot;
    uint32_t nc, myoff;
    if (tot1 >= K_TOP)      { pivot = P1;            nc = tot1;    myoff = texcl & 0xFFFFu; }
    else if (tot2 >= K_TOP) { pivot = P2;            nc = tot2;    myoff = texcl >> 16;     }
    else                    { pivot = -__int_as_float(0x7F800000); nc = ROW_LEN; myoff = (uint32_t)tid * EPT; }

    // ---- compact candidates (order irrelevant; ranking is value-based) ----
    #pragma unroll
    for (int j = 0; j < EPT; ++j) {
        if (v[j] >= pivot) s_cand[myoff++] = v[j];
    }
    __syncthreads();

    // ---- rank candidates: thread holding the K-th largest publishes T ----
    for (uint32_t c = tid; c < nc; c += THREADS) {
        float mk = s_cand[c];
        uint32_t gt = 0, eq = 0;
        #pragma unroll 4
        for (uint32_t i = 0; i < nc; ++i) {       // broadcast LDS reads
            float cv = s_cand[i];
            gt += (cv > mk);
            eq += (cv == mk);
        }
        if (gt < K_TOP && gt + eq >= K_TOP) {     // all T-tie threads write identical values
            s_T = mk;
            s_rem2 = K_TOP - gt;
            s_eq = eq;
        }
    }
    __syncthreads();

    const float    T    = s_T;
    const uint32_t rem2 = s_rem2;
    const uint32_t eqT  = s_eq;

    float o[EPT];
    if (eqT == rem2) {
        // common case: include every value >= T
        #pragma unroll
        for (int j = 0; j < EPT; ++j)
            o[j] = (v[j] >= T) ? v[j] : 0.0f;
    } else {
        // rare: more T-ties than quota -> keep first rem2 by global index
        uint32_t cnt = 0;
        #pragma unroll
        for (int j = 0; j < EPT; ++j) cnt += (v[j] == T);
        uint32_t ti = cnt;
        #pragma unroll
        for (int off = 1; off < 32; off <<= 1) {
            uint32_t n = __shfl_up_sync(0xffffffffu, ti, off);
            if (lane >= off) ti += n;
        }
        if (lane == 31) s_wsum[wid] = ti;
        __syncthreads();
        if (tid < NWARP) {
            uint32_t w = s_wsum[tid];
            #pragma unroll
            for (int off = 1; off < NWARP; off <<= 1) {
                uint32_t n = __shfl_up_sync(0xffffu, w, off);
                if (tid >= off) w += n;
            }
            s_wsum[tid] = w;
        }
        __syncthreads();
        uint32_t rank = ((wid > 0) ? s_wsum[wid - 1] : 0u) + (ti - cnt);
        #pragma unroll
        for (int j = 0; j < EPT; ++j) {
            bool eq = (v[j] == T);
            bool inc = (v[j] > T) || (eq && rank < rem2);
            o[j] = inc ? v[j] : 0.0f;
            rank += eq;
        }
    }

    float4 w0, w1;
    w0.x = o[0]; w0.y = o[1]; w0.z = o[2]; w0.w = o[3];
    w1.x = o[4]; w1.y = o[5]; w1.z = o[6]; w1.w = o[7];
    __stcs(&orow[2 * tid],     w0);
    __stcs(&orow[2 * tid + 1], w1);
}

extern "C" void kernel_launch(void* const* d_in, const int* in_sizes, int n_in,
                              void* d_out, int out_size) {
    const float* x = (const float*)d_in[0];
    float* out = (float*)d_out;
    int rows = in_sizes[0] / ROW_LEN;
    topk_mask_kernel<<<rows, THREADS>>>(x, out);
}

// round 7
// speedup vs baseline: 2.0347x; 1.0015x over previous
#include <cuda_runtime.h>
#include <cstdint>

#define ROW_LEN 4096
#define K_TOP   64u
#define THREADS 512
#define EPT     8
#define NWARP   16

__global__ __launch_bounds__(THREADS, 4)
void topk_mask_kernel(const float* __restrict__ x, float* __restrict__ out) {
    const int row  = blockIdx.x;
    const int tid  = threadIdx.x;
    const int lane = tid & 31;
    const int wid  = tid >> 5;
    const float NEG_INF = __int_as_float(0xFF800000);

    __shared__ __align__(16) float s_cand[ROW_LEN + 4];
    __shared__ uint32_t s_part[4][128];
    __shared__ uint32_t s_wtot[NWARP];
    __shared__ float    s_T;
    __shared__ uint32_t s_rem2, s_eq;
    __shared__ uint32_t s_wsum[NWARP];

    const float4* xrow = reinterpret_cast<const float4*>(x + (size_t)row * ROW_LEN);
    float4*       orow = reinterpret_cast<float4*>(out + (size_t)row * ROW_LEN);

    float4 a = __ldcs(&xrow[2 * tid]);
    float4 b = __ldcs(&xrow[2 * tid + 1]);
    float v[EPT];
    v[0] = a.x; v[1] = a.y; v[2] = a.z; v[3] = a.w;
    v[4] = b.x; v[5] = b.y; v[6] = b.z; v[7] = b.w;

    // ---- leveled pivot: P1 covers 99.9% of rows; P2 ~all; -inf exact fallback ----
    float    pivot = NEG_INF;
    uint32_t nc = ROW_LEN, myoff = (uint32_t)tid * EPT;
    #pragma unroll 1
    for (int lvl = 0; lvl < 3; ++lvl) {
        float p = (lvl == 0) ? 2.0f : ((lvl == 1) ? 1.5f : NEG_INF);
        uint32_t c = 0;
        #pragma unroll
        for (int j = 0; j < EPT; ++j) c += (v[j] >= p);

        uint32_t incl = c;                       // warp inclusive scan
        #pragma unroll
        for (int off = 1; off < 32; off <<= 1) {
            uint32_t n = __shfl_up_sync(0xffffffffu, incl, off);
            if (lane >= off) incl += n;
        }
        if (lane == 31) s_wtot[wid] = incl;
        __syncthreads();

        // redundant 16-lane scan of warp totals in every warp (no 2nd barrier)
        uint32_t wv = (lane < NWARP) ? s_wtot[lane] : 0u;
        #pragma unroll
        for (int off = 1; off < NWARP; off <<= 1) {
            uint32_t n = __shfl_up_sync(0xffffffffu, wv, off);
            if (lane >= off) wv += n;
        }
        uint32_t tot = __shfl_sync(0xffffffffu, wv, NWARP - 1);
        uint32_t wex = 0;
        if (wid > 0) wex = __shfl_sync(0xffffffffu, wv, wid - 1);

        if (tot >= K_TOP) {                      // block-uniform
            pivot = p;
            nc = tot;
            myoff = wex + (incl - c);
            break;
        }
        __syncthreads();                         // rare: protect s_wtot for next level
    }

    // ---- compact candidates + pad to multiple of 4 with -inf ----
    #pragma unroll
    for (int j = 0; j < EPT; ++j)
        if (v[j] >= pivot) s_cand[myoff++] = v[j];
    const uint32_t ncp = (nc + 3u) & ~3u;
    if ((uint32_t)tid < ncp - nc) s_cand[nc + tid] = NEG_INF;
    __syncthreads();

    // ---- rank candidates; thread holding the K-th largest publishes T ----
    const float4* c4 = reinterpret_cast<const float4*>(s_cand);
    const uint32_t nq = ncp >> 2;
    if (nc <= 128u) {
        // 4-way split: c = candidate, h = slice of the comparison range
        const uint32_t c = (uint32_t)tid & 127u;
        const uint32_t h = (uint32_t)tid >> 7;
        const uint32_t q  = (nq + 3u) >> 2;
        const uint32_t i0 = h * q;
        const uint32_t i1 = min(i0 + q, nq);
        float mk = s_cand[c];                    // c>=nc reads junk; publish guarded
        uint32_t gt = 0, eq = 0;
        for (uint32_t i = i0; i < i1; ++i) {     // broadcast LDS.128
            float4 cv = c4[i];
            gt += (cv.x > mk) + (cv.y > mk) + (cv.z > mk) + (cv.w > mk);
            eq += (cv.x == mk) + (cv.y == mk) + (cv.z == mk) + (cv.w == mk);
        }
        s_part[h][c] = gt | (eq << 16);
        __syncthreads();
        if ((uint32_t)tid < nc) {                // combiner == h=0 thread, has mk
            uint32_t s = s_part[0][tid] + s_part[1][tid] + s_part[2][tid] + s_part[3][tid];
            uint32_t g = s & 0xFFFFu, e = s >> 16;
            if (g < K_TOP && g + e >= K_TOP) { s_T = mk; s_rem2 = K_TOP - g; s_eq = e; }
        }
    } else {
        // generic (rare): strided candidates, full comparison range
        for (uint32_t c = tid; c < nc; c += THREADS) {
            float mk = s_cand[c];
            uint32_t gt = 0, eq = 0;
            for (uint32_t i = 0; i < nq; ++i) {
                float4 cv = c4[i];
                gt += (cv.x > mk) + (cv.y > mk) + (cv.z > mk) + (cv.w > mk);
                eq += (cv.x == mk) + (cv.y == mk) + (cv.z == mk) + (cv.w == mk);
            }
            if (gt < K_TOP && gt + eq >= K_TOP) { s_T = mk; s_rem2 = K_TOP - gt; s_eq = eq; }
        }
    }
    __syncthreads();

    const float    T    = s_T;
    const uint32_t rem2 = s_rem2;
    const uint32_t eqT  = s_eq;

    float o[EPT];
    if (eqT == rem2) {
        // common case: include every value >= T
        #pragma unroll
        for (int j = 0; j < EPT; ++j)
            o[j] = (v[j] >= T) ? v[j] : 0.0f;
    } else {
        // rare: more T-ties than quota -> keep first rem2 by global index
        uint32_t cnt = 0;
        #pragma unroll
        for (int j = 0; j < EPT; ++j) cnt += (v[j] == T);
        uint32_t ti = cnt;
        #pragma unroll
        for (int off = 1; off < 32; off <<= 1) {
            uint32_t n = __shfl_up_sync(0xffffffffu, ti, off);
            if (lane >= off) ti += n;
        }
        if (lane == 31) s_wsum[wid] = ti;
        __syncthreads();
        if (tid < NWARP) {
            uint32_t w = s_wsum[tid];
            #pragma unroll
            for (int off = 1; off < NWARP; off <<= 1) {
                uint32_t n = __shfl_up_sync(0xffffu, w, off);
                if (tid >= off) w += n;
            }
            s_wsum[tid] = w;
        }
        __syncthreads();
        uint32_t rank = ((wid > 0) ? s_wsum[wid - 1] : 0u) + (ti - cnt);
        #pragma unroll
        for (int j = 0; j < EPT; ++j) {
            bool eq = (v[j] == T);
            bool inc = (v[j] > T) || (eq && rank < rem2);
            o[j] = inc ? v[j] : 0.0f;
            rank += eq;
        }
    }

    float4 w0, w1;
    w0.x = o[0]; w0.y = o[1]; w0.z = o[2]; w0.w = o[3];
    w1.x = o[4]; w1.y = o[5]; w1.z = o[6]; w1.w = o[7];
    __stcs(&orow[2 * tid],     w0);
    __stcs(&orow[2 * tid + 1], w1);
}

extern "C" void kernel_launch(void* const* d_in, const int* in_sizes, int n_in,
                              void* d_out, int out_size) {
    const float* x = (const float*)d_in[0];
    float* out = (float*)d_out;
    int rows = in_sizes[0] / ROW_LEN;
    topk_mask_kernel<<<rows, THREADS>>>(x, out);
}

// round 9
// speedup vs baseline: 2.1927x; 1.0777x over previous
#include <cuda_runtime.h>
#include <cstdint>

#define ROW_LEN 4096
#define K_TOP   64u
#define THREADS 512
#define EPT     8
#define NWARP   16

__global__ __launch_bounds__(THREADS, 4)
void topk_mask_kernel(const float* __restrict__ x, float* __restrict__ out) {
    const int row  = blockIdx.x;
    const int tid  = threadIdx.x;
    const int lane = tid & 31;
    const int wid  = tid >> 5;
    const float NEG_INF = __int_as_float(0xFF800000);

    __shared__ __align__(16) float s_cand[ROW_LEN + 4];
    __shared__ uint32_t s_part[4][128];
    __shared__ uint32_t s_wtot[NWARP];
    __shared__ uint32_t s_Tbits, s_geT;
    __shared__ uint32_t s_wsum[NWARP];

    const float4* xrow = reinterpret_cast<const float4*>(x + (size_t)row * ROW_LEN);
    float4*       orow = reinterpret_cast<float4*>(out + (size_t)row * ROW_LEN);

    float4 a = __ldcs(&xrow[2 * tid]);
    float4 b = __ldcs(&xrow[2 * tid + 1]);
    if (tid == 0) s_Tbits = 0u;
    float v[EPT];
    v[0] = a.x; v[1] = a.y; v[2] = a.z; v[3] = a.w;
    v[4] = b.x; v[5] = b.y; v[6] = b.z; v[7] = b.w;

    // ---- leveled pivot: P1 covers ~99.9% of rows; P2 ~all; -inf exact fallback ----
    float    pivot = NEG_INF;
    uint32_t nc = ROW_LEN, myoff = (uint32_t)tid * EPT;
    #pragma unroll 1
    for (int lvl = 0; lvl < 3; ++lvl) {
        float p = (lvl == 0) ? 2.0f : ((lvl == 1) ? 1.5f : NEG_INF);
        uint32_t c = 0;
        #pragma unroll
        for (int j = 0; j < EPT; ++j) c += (v[j] >= p);

        uint32_t incl = c;                       // warp inclusive scan
        #pragma unroll
        for (int off = 1; off < 32; off <<= 1) {
            uint32_t n = __shfl_up_sync(0xffffffffu, incl, off);
            if (lane >= off) incl += n;
        }
        if (lane == 31) s_wtot[wid] = incl;
        __syncthreads();

        // redundant 16-lane scan of warp totals in every warp (no 2nd barrier)
        uint32_t wv = (lane < NWARP) ? s_wtot[lane] : 0u;
        #pragma unroll
        for (int off = 1; off < NWARP; off <<= 1) {
            uint32_t n = __shfl_up_sync(0xffffffffu, wv, off);
            if (lane >= off) wv += n;
        }
        uint32_t tot = __shfl_sync(0xffffffffu, wv, NWARP - 1);
        uint32_t wex = 0;
        if (wid > 0) wex = __shfl_sync(0xffffffffu, wv, wid - 1);

        if (tot >= K_TOP) {                      // block-uniform decision
            pivot = p;
            nc = tot;
            myoff = wex + (incl - c);
            break;
        }
        __syncthreads();                         // rare: protect s_wtot for next level
    }

    // ---- compact candidates + pad to multiple of 4 with -inf ----
    #pragma unroll
    for (int j = 0; j < EPT; ++j)
        if (v[j] >= pivot) s_cand[myoff++] = v[j];
    const uint32_t ncp = (nc + 3u) & ~3u;
    if ((uint32_t)tid < ncp - nc) s_cand[nc + tid] = NEG_INF;
    __syncthreads();

    // ---- rank: T = max{ mk : count(cand >= mk) >= K } ----
    const float4* c4 = reinterpret_cast<const float4*>(s_cand);
    const uint32_t nq = ncp >> 2;
    if (nc <= 128u) {
        // fast path: candidates all positive (pivot >= 1.5) -> float bits monotone as uint.
        // 4-way split: c = candidate index, h = slice of the comparison range.
        const uint32_t c = (uint32_t)tid & 127u;
        const uint32_t h = (uint32_t)tid >> 7;
        const uint32_t q  = (nq + 3u) >> 2;
        const uint32_t i0 = h * q;
        const uint32_t i1 = min(i0 + q, nq);
        float mk = s_cand[c];                    // c>=nc reads junk; guarded below
        uint32_t ge = 0;
        for (uint32_t i = i0; i < i1; ++i) {     // broadcast LDS.128, ge-count only
            float4 cv = c4[i];
            ge += (cv.x >= mk) + (cv.y >= mk) + (cv.z >= mk) + (cv.w >= mk);
        }
        s_part[h][c] = ge;
        __syncthreads();
        uint32_t mb = 0, get = 0;
        if ((uint32_t)tid < nc) {
            get = s_part[0][tid] + s_part[1][tid] + s_part[2][tid] + s_part[3][tid];
            if (get >= K_TOP) mb = __float_as_uint(mk);   // positive -> monotone
        }
        uint32_t wmax = __reduce_max_sync(0xffffffffu, mb);
        if (mb == wmax && mb != 0u && get >= K_TOP) {
            // warp winner: one atomic per warp; T-thread also records ge(T)
            atomicMax(&s_Tbits, mb);
        }
        __syncthreads();
        if (mb == s_Tbits && mb != 0u) s_geT = get;   // same value from all T-ties: benign race
    } else {
        // generic (rare, may contain negatives): full gt/eq method
        for (uint32_t c = tid; c < nc; c += THREADS) {
            float mk = s_cand[c];
            uint32_t gt = 0, eq = 0;
            for (uint32_t i = 0; i < nq; ++i) {
                float4 cv = c4[i];
                gt += (cv.x > mk) + (cv.y > mk) + (cv.z > mk) + (cv.w > mk);
                eq += (cv.x == mk) + (cv.y == mk) + (cv.z == mk) + (cv.w == mk);
            }
            if (gt < K_TOP && gt + eq >= K_TOP) {
                s_Tbits = __float_as_uint(mk);   // storage only (not compared)
                s_geT = gt + eq;
            }
        }
    }
    __syncthreads();

    const float    T   = __uint_as_float(s_Tbits);
    const uint32_t geT = s_geT;

    float o[EPT];
    if (geT == K_TOP) {
        // no surplus ties: include every value >= T (the overwhelmingly common case)
        #pragma unroll
        for (int j = 0; j < EPT; ++j)
            o[j] = (v[j] >= T) ? v[j] : 0.0f;
    } else {
        // surplus T-ties: keep first (K - gt) by global index
        uint32_t cnt = 0;
        #pragma unroll
        for (int j = 0; j < EPT; ++j) cnt += (v[j] == T);
        uint32_t ti = cnt;
        #pragma unroll
        for (int off = 1; off < 32; off <<= 1) {
            uint32_t n = __shfl_up_sync(0xffffffffu, ti, off);
            if (lane >= off) ti += n;
        }
        if (lane == 31) s_wsum[wid] = ti;
        __syncthreads();
        if (tid < NWARP) {
            uint32_t w = s_wsum[tid];
            #pragma unroll
            for (int off = 1; off < NWARP; off <<= 1) {
                uint32_t n = __shfl_up_sync(0xffffu, w, off);
                if (tid >= off) w += n;
            }
            s_wsum[tid] = w;
        }
        __syncthreads();
        const uint32_t eqB  = s_wsum[NWARP - 1];        // total == T in row
        const uint32_t rem2 = K_TOP - (geT - eqB);      // quota for ties
        uint32_t rank = ((wid > 0) ? s_wsum[wid - 1] : 0u) + (ti - cnt);
        #pragma unroll
        for (int j = 0; j < EPT; ++j) {
            bool eq = (v[j] == T);
            bool inc = (v[j] > T) || (eq && rank < rem2);
            o[j] = inc ? v[j] : 0.0f;
            rank += eq;
        }
    }

    float4 w0, w1;
    w0.x = o[0]; w0.y = o[1]; w0.z = o[2]; w0.w = o[3];
    w1.x = o[4]; w1.y = o[5]; w1.z = o[6]; w1.w = o[7];
    __stcs(&orow[2 * tid],     w0);
    __stcs(&orow[2 * tid + 1], w1);
}

extern "C" void kernel_launch(void* const* d_in, const int* in_sizes, int n_in,
                              void* d_out, int out_size) {
    const float* x = (const float*)d_in[0];
    float* out = (float*)d_out;
    int rows = in_sizes[0] / ROW_LEN;
    topk_mask_kernel<<<rows, THREADS>>>(x, out);
}